// round 10
// baseline (speedup 1.0000x reference)
#include <cuda_runtime.h>
#include <cuda_bf16.h>

// Problem constants
#define BB 32
#define NN 1024
#define FF 128
#define DD 128
#define DK 0.08838834764831843f  // 128^{-0.5}

#define NBLK 128   // 4 chunk-blocks per batch, 256 rows each
#define NTHR 1024  // 32 warps
#define ROWS 256   // rows per block

// Scratch
__device__ float  g_spart[BB * 4 * FF];   // per-chunk feature sums
__device__ float2 g_ls[BB * 4];           // (lmax, lsumexp) per chunk
__device__ unsigned g_bar;                // monotonic ticket (replay-safe)

// ---------------------------------------------------------------------------
// Software grid barrier (R7-proven form): all-thread fences both sides.
// All 128 blocks co-resident (1 CTA/SM, 148 SMs).
// ---------------------------------------------------------------------------
__device__ __forceinline__ void grid_barrier() {
    __threadfence();
    __syncthreads();
    if (threadIdx.x == 0) {
        unsigned ticket = atomicAdd(&g_bar, 1u);
        unsigned target = (ticket / NBLK + 1u) * NBLK;
        unsigned cur;
        do {
            asm volatile("ld.global.acquire.gpu.u32 %0, [%1];"
                         : "=r"(cur) : "l"(&g_bar));
        } while (cur < target);
    }
    __syncthreads();
    __threadfence();
}

__global__ __launch_bounds__(NTHR, 1) void k_fused(
        const float* __restrict__ aq,
        const float* __restrict__ mask,
        const float* __restrict__ Wq,
        const float* __restrict__ bq,
        const float* __restrict__ Wk,
        const float* __restrict__ bk,
        const float* __restrict__ Wv,
        const float* __restrict__ bv,
        float* __restrict__ out_attn,
        float* __restrict__ out_ctx) {
    int blk = blockIdx.x;
    int b   = blk >> 2;        // batch
    int ch  = blk & 3;         // 256-row chunk
    int tid = threadIdx.x;
    int lane = tid & 31;
    int warp = tid >> 5;       // 0..31

    __shared__ float4 sh4[32][32];     // 16 KB reduce scratch
    __shared__ float  s_sh[FF];
    __shared__ float  ksum_sh[DD];
    __shared__ float  wvec_sh[FF];
    __shared__ float  t_sh[FF];
    __shared__ float  y_sh[DD];
    __shared__ float  l_sh[ROWS];
    __shared__ float  e_sh[ROWS];
    __shared__ float  wt_sh[ROWS];
    __shared__ float  m_sh[ROWS];
    __shared__ float  ctx_part[8][DD]; // 4 KB
    __shared__ float  red[32];
    __shared__ float  red2[32];
    __shared__ float2 ls4_sh[4];
    __shared__ float  bc[4];           // 0=cbias 1=lmax 2=lsum 3=wspart

    const float4* aq4 = reinterpret_cast<const float4*>(aq);
    int rloc0 = warp * 8;
    const float4* base = aq4 + ((size_t)b * NN + ch * ROWS + rloc0) * (FF / 4);

    // ---- P0: zero out_ctx (poisoned); load own mask ----
    if (ch == 0 && tid < DD) out_ctx[b * DD + tid] = 0.f;
    if (tid < ROWS) m_sh[tid] = mask[(size_t)b * NN + ch * ROWS + tid];

    // ---- P1: DRAM read, per-chunk feature sums -> g_spart ----
    {
        float4 v[8];
#pragma unroll
        for (int jj = 0; jj < 8; jj++)
            v[jj] = base[jj * (FF / 4) + lane];
        float4 acc = v[0];
#pragma unroll
        for (int jj = 1; jj < 8; jj++) {
            acc.x += v[jj].x; acc.y += v[jj].y;
            acc.z += v[jj].z; acc.w += v[jj].w;
        }
        sh4[warp][lane] = acc;
        __syncthreads();
        if (warp < 4) {
            float4 r = sh4[warp * 8][lane];
#pragma unroll
            for (int w = 1; w < 8; w++) {
                float4 x = sh4[warp * 8 + w][lane];
                r.x += x.x; r.y += x.y; r.z += x.z; r.w += x.w;
            }
            sh4[warp][lane] = r;
        }
        __syncthreads();
        if (warp == 0) {
            float4 r = sh4[0][lane];
#pragma unroll
            for (int w = 1; w < 4; w++) {
                float4 x = sh4[w][lane];
                r.x += x.x; r.y += x.y; r.z += x.z; r.w += x.w;
            }
            reinterpret_cast<float4*>(&g_spart[(b * 4 + ch) * FF])[lane] = r;
        }
    }

    grid_barrier();   // ==== barrier 1: all g_spart ready ====

    // ---- P2: s, ksum, wvec, cbias — distributed over all 1024 threads ----
    if (tid < FF) {
        float s = 0.f;
#pragma unroll
        for (int c2 = 0; c2 < 4; c2++)
            s += g_spart[(b * 4 + c2) * FF + tid];
        s_sh[tid] = s;
    }
    __syncthreads();
    {   // ksum partials: 8 parts x 128 d
        int d = tid & 127, part = tid >> 7;
        float acc = 0.f;
#pragma unroll
        for (int i = 0; i < 16; i++) {
            int f = part * 16 + i;
            acc += s_sh[f] * Wk[(size_t)f * DD + d];
        }
        ctx_part[part][d] = acc;
    }
    __syncthreads();
    if (tid < DD) {
        float a = 0.f;
#pragma unroll
        for (int p = 0; p < 8; p++) a += ctx_part[p][tid];
        ksum_sh[tid] = a + (float)NN * bk[tid];
    }
    __syncthreads();
    {   // wvec[f]: 8 lanes per f, d = p8 + 8*i
        int f = tid >> 3, p8 = tid & 7;
        float acc = 0.f;
#pragma unroll
        for (int i = 0; i < 16; i++) {
            int d = p8 + 8 * i;
            acc += Wq[(size_t)f * DD + d] * ksum_sh[d];
        }
        acc += __shfl_xor_sync(0xffffffffu, acc, 1);
        acc += __shfl_xor_sync(0xffffffffu, acc, 2);
        acc += __shfl_xor_sync(0xffffffffu, acc, 4);
        if (p8 == 0) wvec_sh[f] = acc;
    }
    if (warp == 0) {   // cbias = bq . ksum
        float p = 0.f;
#pragma unroll
        for (int dd = lane; dd < DD; dd += 32)
            p += bq[dd] * ksum_sh[dd];
        for (int off = 16; off; off >>= 1)
            p += __shfl_xor_sync(0xffffffffu, p, off);
        if (lane == 0) bc[0] = p;
    }
    __syncthreads();

    // ---- P3a: logits, 4 threads per row (L2 reads, populate L1) ----
    {
        int row = tid >> 2, q = tid & 3;
        const float4* rp = aq4 + ((size_t)b * NN + ch * ROWS + row) * (FF / 4)
                         + q * 8;
        const float4* wv4 = reinterpret_cast<const float4*>(wvec_sh) + q * 8;
        float4 x[8];
#pragma unroll
        for (int i = 0; i < 8; i++) x[i] = rp[i];
        float d = 0.f;
#pragma unroll
        for (int i = 0; i < 8; i++) {
            float4 wv = wv4[i];
            d += x[i].x * wv.x + x[i].y * wv.y + x[i].z * wv.z + x[i].w * wv.w;
        }
        d += __shfl_xor_sync(0xffffffffu, d, 1);
        d += __shfl_xor_sync(0xffffffffu, d, 2);
        if (q == 0)
            l_sh[row] = (m_sh[row] != 0.f) ? (DK * (d + bc[0])) : -1e9f;
    }
    __syncthreads();

    // ---- P3 stats: lmax, e, w~, lsum, wspart; publish (lmax, lsum) ----
    {
        float mx = (tid < ROWS) ? l_sh[tid] : -3.4e38f;
        for (int off = 16; off; off >>= 1)
            mx = fmaxf(mx, __shfl_xor_sync(0xffffffffu, mx, off));
        if (lane == 0) red[warp] = mx;
        __syncthreads();
        if (warp == 0) {
            float m2 = red[lane];
            for (int off = 16; off; off >>= 1)
                m2 = fmaxf(m2, __shfl_xor_sync(0xffffffffu, m2, off));
            if (lane == 0) bc[1] = m2;
        }
        __syncthreads();
        float lmax = bc[1];

        float ee = 0.f, wt = 0.f;
        if (tid < ROWS) {
            ee = expf(l_sh[tid] - lmax);
            wt = m_sh[tid] * ee;
            e_sh[tid] = ee;
            wt_sh[tid] = wt;
        }
        float s1 = ee, s2 = wt;
        for (int off = 16; off; off >>= 1) {
            s1 += __shfl_xor_sync(0xffffffffu, s1, off);
            s2 += __shfl_xor_sync(0xffffffffu, s2, off);
        }
        if (lane == 0) { red[warp] = s1; red2[warp] = s2; }
        __syncthreads();
        if (warp == 0) {
            float t1 = red[lane], t2 = red2[lane];
            for (int off = 16; off; off >>= 1) {
                t1 += __shfl_xor_sync(0xffffffffu, t1, off);
                t2 += __shfl_xor_sync(0xffffffffu, t2, off);
            }
            if (lane == 0) { bc[2] = t1; bc[3] = t2; }
        }
        __syncthreads();
        if (tid == 0)
            g_ls[blk] = make_float2(bc[1], bc[2]);   // (lmax, lsum)
    }

    // ---- P3b: local weighted row-sum (L1 hits) -> t_sh ----
    {
        float4 acc = make_float4(0.f, 0.f, 0.f, 0.f);
#pragma unroll
        for (int jj = 0; jj < 8; jj++) {
            float4 x = base[jj * (FF / 4) + lane];
            float w = wt_sh[rloc0 + jj];
            acc.x += w * x.x; acc.y += w * x.y;
            acc.z += w * x.z; acc.w += w * x.w;
        }
        sh4[warp][lane] = acc;
        __syncthreads();
        if (warp < 4) {
            float4 r = sh4[warp * 8][lane];
#pragma unroll
            for (int w = 1; w < 8; w++) {
                float4 x = sh4[warp * 8 + w][lane];
                r.x += x.x; r.y += x.y; r.z += x.z; r.w += x.w;
            }
            sh4[warp][lane] = r;
        }
        __syncthreads();
        if (warp == 0) {
            float4 r = sh4[0][lane];
#pragma unroll
            for (int w = 1; w < 4; w++) {
                float4 x = sh4[w][lane];
                r.x += x.x; r.y += x.y; r.z += x.z; r.w += x.w;
            }
            reinterpret_cast<float4*>(t_sh)[lane] = r;
        }
        __syncthreads();
    }

    // ---- P3c: y_part = t_part @ Wv (distributed) ----
    {
        int d = tid & 127, part = tid >> 7;
        float acc = 0.f;
#pragma unroll
        for (int i = 0; i < 16; i++) {
            int f = part * 16 + i;
            acc += t_sh[f] * Wv[(size_t)f * DD + d];
        }
        ctx_part[part][d] = acc;
    }
    __syncthreads();
    if (tid < DD) {
        float a = 0.f;
#pragma unroll
        for (int p = 0; p < 8; p++) a += ctx_part[p][tid];
        y_sh[tid] = a;
    }

    grid_barrier();   // ==== barrier 2: all (lmax, lsum) ready ====

    // ---- P4: tiny finalize — combine stats, scale own outputs ----
    if (tid < 4) ls4_sh[tid] = g_ls[b * 4 + tid];
    __syncthreads();
    {
        float gmax = ls4_sh[0].x;
#pragma unroll
        for (int i = 1; i < 4; i++) gmax = fmaxf(gmax, ls4_sh[i].x);
        float gsum = 0.f;
#pragma unroll
        for (int i = 0; i < 4; i++)
            gsum += expf(ls4_sh[i].x - gmax) * ls4_sh[i].y;
        float alpha = expf(ls4_sh[ch].x - gmax) / gsum;

        if (tid < ROWS)
            out_attn[(size_t)b * NN + ch * ROWS + tid] = e_sh[tid] * alpha;
        if (tid < DD)
            atomicAdd(&out_ctx[(size_t)b * DD + tid],
                      alpha * (y_sh[tid] + bc[3] * bv[tid]));
    }
}

// ---------------------------------------------------------------------------
// Inputs: atom_query, mask, Wq, bq, Wk, bk, Wv, bv
// Output: attn [B*N] then context [B*D], float32.
// ---------------------------------------------------------------------------
extern "C" void kernel_launch(void* const* d_in, const int* in_sizes, int n_in,
                              void* d_out, int out_size) {
    const float* aq   = (const float*)d_in[0];
    const float* mask = (const float*)d_in[1];
    const float* Wq   = (const float*)d_in[2];
    const float* bq   = (const float*)d_in[3];
    const float* Wk   = (const float*)d_in[4];
    const float* bk   = (const float*)d_in[5];
    const float* Wv   = (const float*)d_in[6];
    const float* bv   = (const float*)d_in[7];

    float* out_attn = (float*)d_out;
    float* out_ctx  = out_attn + (size_t)BB * NN;

    k_fused<<<NBLK, NTHR>>>(aq, mask, Wq, bq, Wk, bk, Wv, bv,
                            out_attn, out_ctx);
}

// round 13
// speedup vs baseline: 1.3589x; 1.3589x over previous
#include <cuda_runtime.h>
#include <cuda_bf16.h>

// Problem constants
#define BB 32
#define NN 1024
#define FF 128
#define DD 128
#define DK 0.08838834764831843f  // 128^{-0.5}

#define NBLK 128   // 4 chunk-blocks per batch, 256 rows each
#define NTHR 1024  // 32 warps
#define ROWS 256   // rows per block

// Scratch
__device__ float  g_spart[BB * 4 * FF];   // per-chunk feature sums
__device__ float2 g_ls[BB * 4];           // (lmax, lsumexp) per chunk
__device__ unsigned g_bar;                // monotonic ticket (replay-safe)

// ---------------------------------------------------------------------------
// Software grid barrier (R7-proven form): all-thread fences both sides.
// All 128 blocks co-resident (1 CTA/SM, 148 SMs).
// ---------------------------------------------------------------------------
__device__ __forceinline__ void grid_barrier() {
    __threadfence();
    __syncthreads();
    if (threadIdx.x == 0) {
        unsigned ticket = atomicAdd(&g_bar, 1u);
        unsigned target = (ticket / NBLK + 1u) * NBLK;
        unsigned cur;
        do {
            asm volatile("ld.global.acquire.gpu.u32 %0, [%1];"
                         : "=r"(cur) : "l"(&g_bar));
        } while (cur < target);
    }
    __syncthreads();
    __threadfence();
}

__global__ __launch_bounds__(NTHR, 1) void k_fused(
        const float* __restrict__ aq,
        const float* __restrict__ mask,
        const float* __restrict__ Wq,
        const float* __restrict__ bq,
        const float* __restrict__ Wk,
        const float* __restrict__ bk,
        const float* __restrict__ Wv,
        const float* __restrict__ bv,
        float* __restrict__ out_attn,
        float* __restrict__ out_ctx) {
    int blk = blockIdx.x;
    int b   = blk >> 2;        // batch
    int ch  = blk & 3;         // 256-row chunk
    int tid = threadIdx.x;
    int lane = tid & 31;
    int warp = tid >> 5;       // 0..31

    __shared__ float4 sh4[32][32];     // 16 KB reduce scratch
    __shared__ float  s_sh[FF];
    __shared__ float  ksum_sh[DD];
    __shared__ float  wvec_sh[FF];
    __shared__ float  t_sh[FF];
    __shared__ float  y_sh[DD];
    __shared__ float  l_sh[ROWS];
    __shared__ float  e_sh[ROWS];
    __shared__ float  wt_sh[ROWS];
    __shared__ float  m_sh[ROWS];
    __shared__ float  ctx_part[8][DD]; // 4 KB
    __shared__ float  red[32];
    __shared__ float  red2[32];
    __shared__ float2 ls4_sh[4];
    __shared__ float  bc[4];           // 0=cbias 1=lmax 2=lsum 3=wspart

    const float4* aq4 = reinterpret_cast<const float4*>(aq);
    int rloc0 = warp * 8;
    const float4* base = aq4 + ((size_t)b * NN + ch * ROWS + rloc0) * (FF / 4);

    // ---- P0: zero out_ctx (poisoned); load own mask ----
    if (ch == 0 && tid < DD) out_ctx[b * DD + tid] = 0.f;
    if (tid < ROWS) m_sh[tid] = mask[(size_t)b * NN + ch * ROWS + tid];

    // ---- P1: single DRAM read of aq; rows stay in registers v[8] ----
    float4 v[8];
#pragma unroll
    for (int jj = 0; jj < 8; jj++)
        v[jj] = base[jj * (FF / 4) + lane];
    {
        float4 acc = v[0];
#pragma unroll
        for (int jj = 1; jj < 8; jj++) {
            acc.x += v[jj].x; acc.y += v[jj].y;
            acc.z += v[jj].z; acc.w += v[jj].w;
        }
        sh4[warp][lane] = acc;
        __syncthreads();
        if (warp < 4) {
            float4 r = sh4[warp * 8][lane];
#pragma unroll
            for (int w = 1; w < 8; w++) {
                float4 x = sh4[warp * 8 + w][lane];
                r.x += x.x; r.y += x.y; r.z += x.z; r.w += x.w;
            }
            sh4[warp][lane] = r;
        }
        __syncthreads();
        if (warp == 0) {
            float4 r = sh4[0][lane];
#pragma unroll
            for (int w = 1; w < 4; w++) {
                float4 x = sh4[w][lane];
                r.x += x.x; r.y += x.y; r.z += x.z; r.w += x.w;
            }
            reinterpret_cast<float4*>(&g_spart[(b * 4 + ch) * FF])[lane] = r;
        }
    }

    grid_barrier();   // ==== barrier 1: all g_spart ready (v[] stays live) ====

    // ---- P2: s, ksum, wvec, cbias — distributed over all 1024 threads ----
    if (tid < FF) {
        float s = 0.f;
#pragma unroll
        for (int c2 = 0; c2 < 4; c2++)
            s += g_spart[(b * 4 + c2) * FF + tid];
        s_sh[tid] = s;
    }
    __syncthreads();
    {   // ksum partials: 8 parts x 128 d
        int d = tid & 127, part = tid >> 7;
        float acc = 0.f;
#pragma unroll
        for (int i = 0; i < 16; i++) {
            int f = part * 16 + i;
            acc += s_sh[f] * Wk[(size_t)f * DD + d];
        }
        ctx_part[part][d] = acc;
    }
    __syncthreads();
    if (tid < DD) {
        float a = 0.f;
#pragma unroll
        for (int p = 0; p < 8; p++) a += ctx_part[p][tid];
        ksum_sh[tid] = a + (float)NN * bk[tid];
    }
    __syncthreads();
    {   // wvec[f]: 8 lanes per f
        int f = tid >> 3, p8 = tid & 7;
        float acc = 0.f;
#pragma unroll
        for (int i = 0; i < 16; i++) {
            int d = p8 + 8 * i;
            acc += Wq[(size_t)f * DD + d] * ksum_sh[d];
        }
        acc += __shfl_xor_sync(0xffffffffu, acc, 1);
        acc += __shfl_xor_sync(0xffffffffu, acc, 2);
        acc += __shfl_xor_sync(0xffffffffu, acc, 4);
        if (p8 == 0) wvec_sh[f] = acc;
    }
    if (warp == 0) {   // cbias = bq . ksum
        float p = 0.f;
#pragma unroll
        for (int dd = lane; dd < DD; dd += 32)
            p += bq[dd] * ksum_sh[dd];
        for (int off = 16; off; off >>= 1)
            p += __shfl_xor_sync(0xffffffffu, p, off);
        if (lane == 0) bc[0] = p;
    }
    __syncthreads();

    // ---- P3: logits from registers (warp shuffle per row) ----
    {
        float4 wv4 = reinterpret_cast<const float4*>(wvec_sh)[lane];
        float cb = bc[0];
        float mine = 0.f;
#pragma unroll
        for (int jj = 0; jj < 8; jj++) {
            float d = v[jj].x * wv4.x + v[jj].y * wv4.y
                    + v[jj].z * wv4.z + v[jj].w * wv4.w;
            for (int off = 16; off; off >>= 1)
                d += __shfl_xor_sync(0xffffffffu, d, off);
            if (lane == jj) mine = DK * (d + cb);
        }
        if (lane < 8) {
            float m = m_sh[rloc0 + lane];
            l_sh[rloc0 + lane] = (m != 0.f) ? mine : -1e9f;
        }
    }
    __syncthreads();

    // ---- P3 stats: lmax, e, wt, lsum, wspart; publish (lmax, lsum) ----
    {
        float mx = (tid < ROWS) ? l_sh[tid] : -3.4e38f;
        for (int off = 16; off; off >>= 1)
            mx = fmaxf(mx, __shfl_xor_sync(0xffffffffu, mx, off));
        if (lane == 0) red[warp] = mx;
        __syncthreads();
        if (warp == 0) {
            float m2 = red[lane];
            for (int off = 16; off; off >>= 1)
                m2 = fmaxf(m2, __shfl_xor_sync(0xffffffffu, m2, off));
            if (lane == 0) bc[1] = m2;
        }
        __syncthreads();
        float lmax = bc[1];

        float ee = 0.f, wt = 0.f;
        if (tid < ROWS) {
            ee = expf(l_sh[tid] - lmax);
            wt = m_sh[tid] * ee;
            e_sh[tid] = ee;
            wt_sh[tid] = wt;
        }
        float s1 = ee, s2 = wt;
        for (int off = 16; off; off >>= 1) {
            s1 += __shfl_xor_sync(0xffffffffu, s1, off);
            s2 += __shfl_xor_sync(0xffffffffu, s2, off);
        }
        if (lane == 0) { red[warp] = s1; red2[warp] = s2; }
        __syncthreads();
        if (warp == 0) {
            float t1 = red[lane], t2 = red2[lane];
            for (int off = 16; off; off >>= 1) {
                t1 += __shfl_xor_sync(0xffffffffu, t1, off);
                t2 += __shfl_xor_sync(0xffffffffu, t2, off);
            }
            if (lane == 0) { bc[2] = t1; bc[3] = t2; }
        }
        __syncthreads();
        if (tid == 0)
            g_ls[blk] = make_float2(bc[1], bc[2]);   // (lmax, lsum)
    }

    // ---- P3b: weighted row-sum from registers -> t_sh ----
    {
        float4 acc = make_float4(0.f, 0.f, 0.f, 0.f);
#pragma unroll
        for (int jj = 0; jj < 8; jj++) {
            float w = wt_sh[rloc0 + jj];
            acc.x += w * v[jj].x; acc.y += w * v[jj].y;
            acc.z += w * v[jj].z; acc.w += w * v[jj].w;
        }
        sh4[warp][lane] = acc;
        __syncthreads();
        if (warp < 4) {
            float4 r = sh4[warp * 8][lane];
#pragma unroll
            for (int w = 1; w < 8; w++) {
                float4 x = sh4[warp * 8 + w][lane];
                r.x += x.x; r.y += x.y; r.z += x.z; r.w += x.w;
            }
            sh4[warp][lane] = r;
        }
        __syncthreads();
        if (warp == 0) {
            float4 r = sh4[0][lane];
#pragma unroll
            for (int w = 1; w < 4; w++) {
                float4 x = sh4[w][lane];
                r.x += x.x; r.y += x.y; r.z += x.z; r.w += x.w;
            }
            reinterpret_cast<float4*>(t_sh)[lane] = r;
        }
        __syncthreads();
    }

    // ---- P3c: y_part = t_part @ Wv (distributed) ----
    {
        int d = tid & 127, part = tid >> 7;
        float acc = 0.f;
#pragma unroll
        for (int i = 0; i < 16; i++) {
            int f = part * 16 + i;
            acc += t_sh[f] * Wv[(size_t)f * DD + d];
        }
        ctx_part[part][d] = acc;
    }
    __syncthreads();
    if (tid < DD) {
        float a = 0.f;
#pragma unroll
        for (int p = 0; p < 8; p++) a += ctx_part[p][tid];
        y_sh[tid] = a;
    }

    grid_barrier();   // ==== barrier 2: all (lmax, lsum) ready ====

    // ---- P4: tiny finalize — combine stats, scale own outputs ----
    if (tid < 4) ls4_sh[tid] = g_ls[b * 4 + tid];
    __syncthreads();
    {
        float gmax = ls4_sh[0].x;
#pragma unroll
        for (int i = 1; i < 4; i++) gmax = fmaxf(gmax, ls4_sh[i].x);
        float gsum = 0.f;
#pragma unroll
        for (int i = 0; i < 4; i++)
            gsum += expf(ls4_sh[i].x - gmax) * ls4_sh[i].y;
        float alpha = expf(ls4_sh[ch].x - gmax) / gsum;

        if (tid < ROWS)
            out_attn[(size_t)b * NN + ch * ROWS + tid] = e_sh[tid] * alpha;
        if (tid < DD)
            atomicAdd(&out_ctx[(size_t)b * DD + tid],
                      alpha * (y_sh[tid] + bc[3] * bv[tid]));
    }
}

// ---------------------------------------------------------------------------
// Inputs: atom_query, mask, Wq, bq, Wk, bk, Wv, bv
// Output: attn [B*N] then context [B*D], float32.
// ---------------------------------------------------------------------------
extern "C" void kernel_launch(void* const* d_in, const int* in_sizes, int n_in,
                              void* d_out, int out_size) {
    const float* aq   = (const float*)d_in[0];
    const float* mask = (const float*)d_in[1];
    const float* Wq   = (const float*)d_in[2];
    const float* bq   = (const float*)d_in[3];
    const float* Wk   = (const float*)d_in[4];
    const float* bk   = (const float*)d_in[5];
    const float* Wv   = (const float*)d_in[6];
    const float* bv   = (const float*)d_in[7];

    float* out_attn = (float*)d_out;
    float* out_ctx  = out_attn + (size_t)BB * NN;

    k_fused<<<NBLK, NTHR>>>(aq, mask, Wq, bq, Wk, bk, Wv, bv,
                            out_attn, out_ctx);
}